// round 1
// baseline (speedup 1.0000x reference)
#include <cuda_runtime.h>
#include <math_constants.h>

#define SEQ 1024
#define BSZ 8
#define EMBED 512
#define NH 8
#define QHD 32
#define PD 4
#define IN_PROJ 544

// Scratch for projected q/k/p, laid out [b][h][s][d] so kernel 2 streams contiguously.
__device__ float g_Q[BSZ * NH * SEQ * QHD];   // 8 MB
__device__ float g_K[BSZ * NH * SEQ * QHD];   // 8 MB
__device__ float g_P[BSZ * NH * SEQ * PD];    // 1 MB

// ---------------------------------------------------------------------------
// Kernel 1: xp = x @ W^T + b, scattered into g_Q / g_K / g_P.
// x: (S,B,E) row-major -> M = S*B = 8192 rows. W: (544,512). Tiles 64x64, BK=16.
// ---------------------------------------------------------------------------
__global__ __launch_bounds__(256) void proj_kernel(
    const float* __restrict__ x, const float* __restrict__ W,
    const float* __restrict__ bias)
{
    __shared__ float As[16][64];
    __shared__ float Bs[16][64];

    const int tid = threadIdx.x;
    const int m0 = blockIdx.y * 64;
    const int n0 = blockIdx.x * 64;
    const int tx = tid & 15;        // 0..15 -> 4 n-cols
    const int ty = tid >> 4;        // 0..15 -> 4 m-rows
    const int lr = tid >> 2;        // 0..63 row for staging
    const int lc = (tid & 3) * 4;   // 0/4/8/12 col for staging

    float acc[4][4];
#pragma unroll
    for (int i = 0; i < 4; i++)
#pragma unroll
        for (int j = 0; j < 4; j++) acc[i][j] = 0.f;

    for (int k0 = 0; k0 < EMBED; k0 += 16) {
        float4 av = *(const float4*)&x[(size_t)(m0 + lr) * EMBED + k0 + lc];
        float4 bv = make_float4(0.f, 0.f, 0.f, 0.f);
        if (n0 + lr < IN_PROJ)
            bv = *(const float4*)&W[(size_t)(n0 + lr) * EMBED + k0 + lc];
        As[lc + 0][lr] = av.x; As[lc + 1][lr] = av.y;
        As[lc + 2][lr] = av.z; As[lc + 3][lr] = av.w;
        Bs[lc + 0][lr] = bv.x; Bs[lc + 1][lr] = bv.y;
        Bs[lc + 2][lr] = bv.z; Bs[lc + 3][lr] = bv.w;
        __syncthreads();
#pragma unroll
        for (int k = 0; k < 16; k++) {
            float4 a = *(const float4*)&As[k][ty * 4];
            float4 b = *(const float4*)&Bs[k][tx * 4];
            float aa[4] = {a.x, a.y, a.z, a.w};
            float bb[4] = {b.x, b.y, b.z, b.w};
#pragma unroll
            for (int i = 0; i < 4; i++)
#pragma unroll
                for (int j = 0; j < 4; j++) acc[i][j] += aa[i] * bb[j];
        }
        __syncthreads();
    }

#pragma unroll
    for (int i = 0; i < 4; i++) {
        const int m = m0 + ty * 4 + i;
        const int s = m >> 3;      // row index in x is s*B + b
        const int bb = m & 7;
#pragma unroll
        for (int j = 0; j < 4; j++) {
            const int n = n0 + tx * 4 + j;
            if (n >= IN_PROJ) continue;
            const float v = acc[i][j] + bias[n];
            if (n < 256) {
                const int h = n >> 5, d = n & 31;
                g_Q[(((size_t)(bb * NH + h)) * SEQ + s) * QHD + d] = v;
            } else if (n < 512) {
                const int g = n - 256;
                const int h = g >> 5, d = g & 31;
                g_K[(((size_t)(bb * NH + h)) * SEQ + s) * QHD + d] = v;
            } else {
                const int g = n - 512;
                const int h = g >> 2, d = g & 3;
                g_P[(((size_t)(bb * NH + h)) * SEQ + s) * PD + d] = v;
            }
        }
    }
}

// ---------------------------------------------------------------------------
// Kernel 2: per (b, h, 32-row t-tile): scores = QK^T + pos + offset over full
// s = 1024 in SMEM, then row softmax, single write of normalized weights.
// ---------------------------------------------------------------------------
#define TT 32
#define SC 128
// SMEM float layout
#define KS_OFF (TT * SEQ)               // 32768
#define QS_OFF (KS_OFF + SC * 36)       // 37376  (K chunk padded: 9 float4/row)
#define PS_OFF (QS_OFF + TT * QHD)      // 38400
#define SMEM_FLOATS (PS_OFF + TT * PD)  // 38528 -> 154112 bytes

__global__ __launch_bounds__(256) void attn_kernel(
    const float* __restrict__ pos, const float* __restrict__ off,
    float* __restrict__ out)
{
    extern __shared__ float sm[];
    float* sc = sm;                                 // [TT][SEQ]
    float4* Ks4 = (float4*)(sm + KS_OFF);           // [SC][9] (8 used + pad)
    float4* Qs4 = (float4*)(sm + QS_OFF);           // [TT][8]
    float4* Ps4 = (float4*)(sm + PS_OFF);           // [TT]

    const int tid = threadIdx.x;
    const int t0 = blockIdx.x * TT;
    const int h = blockIdx.y;
    const int b = blockIdx.z;

    const float* Qg = g_Q + ((size_t)(b * NH + h)) * SEQ * QHD;
    const float* Kg = g_K + ((size_t)(b * NH + h)) * SEQ * QHD;
    const float* Pg = g_P + ((size_t)(b * NH + h)) * SEQ * PD;

    // Stage Q tile (32x32 floats) and P vectors once.
    {
        const int r = tid >> 3, d4 = tid & 7;
        Qs4[r * 8 + d4] = *(const float4*)&Qg[(size_t)(t0 + r) * QHD + d4 * 4];
        if (tid < TT)
            Ps4[tid] = *(const float4*)&Pg[(size_t)(t0 + tid) * PD];
    }

    const int cl = tid & 63;   // s-lane within chunk (handles s=cl and s=cl+64)
    const int tg = tid >> 6;   // 0..3 -> owns 8 t-rows

    for (int s0 = 0; s0 < SEQ; s0 += SC) {
        __syncthreads();   // protect Ks reuse (and Q/P staging on first iter)
#pragma unroll
        for (int i = tid; i < SC * 8; i += 256) {
            const int s = i >> 3, d4 = i & 7;
            Ks4[s * 9 + d4] = *(const float4*)&Kg[(size_t)(s0 + s) * QHD + d4 * 4];
        }
        __syncthreads();

        float acc0[8], acc1[8];
#pragma unroll
        for (int r = 0; r < 8; r++) { acc0[r] = 0.f; acc1[r] = 0.f; }

#pragma unroll
        for (int d4 = 0; d4 < 8; d4++) {
            const float4 k0 = Ks4[cl * 9 + d4];
            const float4 k1 = Ks4[(cl + 64) * 9 + d4];
#pragma unroll
            for (int r = 0; r < 8; r++) {
                const float4 q = Qs4[(tg * 8 + r) * 8 + d4];
                acc0[r] += q.x * k0.x + q.y * k0.y + q.z * k0.z + q.w * k0.w;
                acc1[r] += q.x * k1.x + q.y * k1.y + q.z * k1.z + q.w * k1.w;
            }
        }

#pragma unroll
        for (int r = 0; r < 8; r++) {
            const int t = tg * 8 + r;
            const int tglob = t0 + t;
            const float4 p = Ps4[t];
            {
                const int s = s0 + cl;
                const float4 pe = *(const float4*)&pos[((size_t)tglob * SEQ + s) * PD];
                const float o = off[((size_t)b * SEQ + tglob) * SEQ + s];
                sc[t * SEQ + s] =
                    acc0[r] + p.x * pe.x + p.y * pe.y + p.z * pe.z + p.w * pe.w + o;
            }
            {
                const int s = s0 + cl + 64;
                const float4 pe = *(const float4*)&pos[((size_t)tglob * SEQ + s) * PD];
                const float o = off[((size_t)b * SEQ + tglob) * SEQ + s];
                sc[t * SEQ + s] =
                    acc1[r] + p.x * pe.x + p.y * pe.y + p.z * pe.z + p.w * pe.w + o;
            }
        }
    }
    __syncthreads();

    // Row softmax: warp w owns rows 4w..4w+3. Strided float4 (lane + 32k) keeps
    // each 8-lane LDS.128 phase on distinct banks.
    const int warp = tid >> 5, lane = tid & 31;
#pragma unroll
    for (int rr = 0; rr < 4; rr++) {
        const int t = warp * 4 + rr;
        float4* row = (float4*)&sc[t * SEQ];   // 256 float4

        float m = -CUDART_INF_F;
#pragma unroll
        for (int k = 0; k < 8; k++) {
            const float4 v = row[lane + 32 * k];
            m = fmaxf(m, fmaxf(fmaxf(v.x, v.y), fmaxf(v.z, v.w)));
        }
#pragma unroll
        for (int o_ = 16; o_ > 0; o_ >>= 1)
            m = fmaxf(m, __shfl_xor_sync(0xffffffffu, m, o_));

        float sum = 0.f;
#pragma unroll
        for (int k = 0; k < 8; k++) {
            float4 v = row[lane + 32 * k];
            v.x = __expf(v.x - m); v.y = __expf(v.y - m);
            v.z = __expf(v.z - m); v.w = __expf(v.w - m);
            row[lane + 32 * k] = v;
            sum += v.x + v.y + v.z + v.w;
        }
#pragma unroll
        for (int o_ = 16; o_ > 0; o_ >>= 1)
            sum += __shfl_xor_sync(0xffffffffu, sum, o_);
        const float inv = 1.0f / sum;

        float4* orow = (float4*)&out[(((size_t)h * BSZ + b) * SEQ + (t0 + t)) * SEQ];
#pragma unroll
        for (int k = 0; k < 8; k++) {
            float4 v = row[lane + 32 * k];
            v.x *= inv; v.y *= inv; v.z *= inv; v.w *= inv;
            orow[lane + 32 * k] = v;
        }
    }
}

// ---------------------------------------------------------------------------
extern "C" void kernel_launch(void* const* d_in, const int* in_sizes, int n_in,
                              void* d_out, int out_size)
{
    const float* x    = (const float*)d_in[0];
    const float* pos  = (const float*)d_in[1];
    const float* off  = (const float*)d_in[2];
    const float* W    = (const float*)d_in[3];
    const float* bias = (const float*)d_in[4];
    float* out = (float*)d_out;

    cudaFuncSetAttribute(attn_kernel, cudaFuncAttributeMaxDynamicSharedMemorySize,
                         SMEM_FLOATS * (int)sizeof(float));

    dim3 gproj((IN_PROJ + 63) / 64, (SEQ * BSZ) / 64);   // 9 x 128
    proj_kernel<<<gproj, 256>>>(x, W, bias);

    dim3 gattn(SEQ / TT, NH, BSZ);                        // 32 x 8 x 8
    attn_kernel<<<gattn, 256, SMEM_FLOATS * (int)sizeof(float)>>>(pos, off, out);
}